// round 14
// baseline (speedup 1.0000x reference)
#include <cuda_runtime.h>
#include <cuda_fp16.h>
#include <math.h>
#include <stdint.h>

#define NB   64
#define LSEQ 1024
#define DIM  64
#define DQK  32
#define BQ   128
#define BK   64

// Scratch (device globals: no allocation allowed in kernel_launch)
__device__ __half g_k [NB*LSEQ*DQK];
__device__ __half g_vT[NB*DIM*LSEQ];    // [b][d][seq]  (pre-transposed V)

__device__ __forceinline__ float quad_sum(float v) {
    v += __shfl_xor_sync(0xffffffffu, v, 1);
    v += __shfl_xor_sync(0xffffffffu, v, 2);
    return v;
}

// packed half2 exp2, degree-2 (Chebyshev on [-0.5,0.5], rel err ~2e-3).
__device__ __forceinline__ uint32_t h2_exp2_pk(__half2 x) {
    const __half2 MAGIC = __float2half2_rn(1536.0f);      // 2^10 + 2^9
    const __half2 C2 = __float2half2_rn(0.2426560f);
    const __half2 C1 = __float2half2_rn(0.7037440f);
    const __half2 C0 = __float2half2_rn(0.9999230f);
    __half2 nf = __hadd2(x, MAGIC);
    __half2 n  = __hsub2(nf, MAGIC);
    __half2 f  = __hsub2(x, n);
    __half2 p  = __hfma2(C2, f, C1);
    p = __hfma2(p, f, C0);
    uint32_t u  = *(uint32_t*)&nf;
    uint32_t sc = ((u - 0x65F165F1u) & 0x001F001Fu) << 10;
    __half2 s = *(__half2*)&sc;
    __half2 r = __hmul2(p, s);
    return *(uint32_t*)&r;
}

// m16n8k16 f16 mma, fp32 accum.
__device__ __forceinline__ void mma_f16(float c[4], const uint32_t a[4],
                                        uint32_t b0, uint32_t b1) {
    asm volatile(
        "mma.sync.aligned.m16n8k16.row.col.f32.f16.f16.f32 "
        "{%0,%1,%2,%3}, {%4,%5,%6,%7}, {%8,%9}, {%0,%1,%2,%3};"
        : "+f"(c[0]), "+f"(c[1]), "+f"(c[2]), "+f"(c[3])
        : "r"(a[0]), "r"(a[1]), "r"(a[2]), "r"(a[3]), "r"(b0), "r"(b1));
}

// m16n8k16 f16 mma, fp16 accum: C packed half2, c[0]=rows g, c[1]=rows g+8.
__device__ __forceinline__ void mma_f16h(uint32_t c[2], const uint32_t a[4],
                                         uint32_t b0, uint32_t b1) {
    asm volatile(
        "mma.sync.aligned.m16n8k16.row.col.f16.f16.f16.f16 "
        "{%0,%1}, {%2,%3,%4,%5}, {%6,%7}, {%0,%1};"
        : "+r"(c[0]), "+r"(c[1])
        : "r"(a[0]), "r"(a[1]), "r"(a[2]), "r"(a[3]), "r"(b0), "r"(b1));
}

__device__ __forceinline__ void ldsm_x4(uint32_t& r0, uint32_t& r1,
                                        uint32_t& r2, uint32_t& r3,
                                        uint32_t addr) {
    asm volatile("ldmatrix.sync.aligned.m8n8.x4.shared.b16 {%0,%1,%2,%3}, [%4];"
        : "=r"(r0), "=r"(r1), "=r"(r2), "=r"(r3) : "r"(addr));
}

__device__ __forceinline__ uint32_t smem_u32(const void* p) {
    return (uint32_t)__cvta_generic_to_shared(p);
}

__device__ __forceinline__ void cp_async16(uint32_t dst, const void* src) {
    asm volatile("cp.async.cg.shared.global [%0], [%1], 16;"
                 :: "r"(dst), "l"(src) : "memory");
}
#define CP_COMMIT() asm volatile("cp.async.commit_group;" ::: "memory")
#define CP_WAIT(n)  asm volatile("cp.async.wait_group %0;" :: "n"(n) : "memory")

__device__ __forceinline__ uint32_t packh2(float lo, float hi) {
    __half2 h = __floats2half2_rn(lo, hi);
    return *(uint32_t*)&h;
}

#define WST 72   // weight smem stride (halfs), rows=n, cols=k
#define OST 40   // outw smem stride (halfs), rows=n(64), cols=k(32)
#define VS_ST 66 // v transpose-staging stride (halfs)

// ---------------------------------------------------------------------------
// Tensorized y-side (unchanged from round 13, validated ~9.5us).
// ---------------------------------------------------------------------------
__global__ void __launch_bounds__(256) ln_proj_y_tc(
    const float* __restrict__ y,
    const float* __restrict__ ln2w, const float* __restrict__ ln2b,
    const float* __restrict__ kw,   const float* __restrict__ kb,
    const float* __restrict__ vw,   const float* __restrict__ vb,
    float*  __restrict__ outyn,
    __half* __restrict__ out_k,
    __half* __restrict__ out_vT)
{
    __shared__ __half kwh[32*WST];
    __shared__ __half vwh[64*WST];
    __shared__ __half v_s[128*VS_ST];
    __shared__ float lnw_s[64], lnb_s[64], kb_s[32], vb_s[64];

    int tid = threadIdx.x;
    int warp = tid >> 5, lane = tid & 31;
    int g = lane >> 2, tg = lane & 3;
    int R0 = warp * 16;
    int r0g = R0 + g, r1g = R0 + 8 + g;
    int lj = lane >> 3, lr = lane & 7;
    long base_row = (long)blockIdx.x * 128;

    for (int i = tid; i < 32*64; i += 256)
        kwh[(i>>6)*WST + (i&63)] = __float2half_rn(kw[i]);
    for (int i = tid; i < 64*64; i += 256)
        vwh[(i>>6)*WST + (i&63)] = __float2half_rn(vw[i]);
    if (tid < 64)      { lnw_s[tid]=ln2w[tid]; lnb_s[tid]=ln2b[tid]; vb_s[tid]=vb[tid]; }
    else if (tid < 96) { kb_s[tid-64]=kb[tid-64]; }

    float yv[8][4];
    const float* ypb = y + base_row*64;
    #pragma unroll
    for (int t = 0; t < 8; t++) {
        int c = t*8 + 2*tg;
        float2 v0 = *(const float2*)&ypb[(long)r0g*64 + c];
        float2 v1 = *(const float2*)&ypb[(long)r1g*64 + c];
        yv[t][0]=v0.x; yv[t][1]=v0.y; yv[t][2]=v1.x; yv[t][3]=v1.y;
    }
    __syncthreads();

    {
        float s0=0, ss0=0, s1=0, ss1=0;
        #pragma unroll
        for (int t = 0; t < 8; t++) {
            s0 += yv[t][0]+yv[t][1]; ss0 += yv[t][0]*yv[t][0]+yv[t][1]*yv[t][1];
            s1 += yv[t][2]+yv[t][3]; ss1 += yv[t][2]*yv[t][2]+yv[t][3]*yv[t][3];
        }
        s0 = quad_sum(s0); ss0 = quad_sum(ss0);
        s1 = quad_sum(s1); ss1 = quad_sum(ss1);
        float mu0 = s0*(1.0f/64.0f), mu1 = s1*(1.0f/64.0f);
        float iv0 = rsqrtf(ss0*(1.0f/64.0f) - mu0*mu0 + 1e-5f);
        float iv1 = rsqrtf(ss1*(1.0f/64.0f) - mu1*mu1 + 1e-5f);
        #pragma unroll
        for (int t = 0; t < 8; t++) {
            int c = t*8 + 2*tg;
            float w0 = lnw_s[c], w1 = lnw_s[c+1];
            float b0v= lnb_s[c], b1v= lnb_s[c+1];
            yv[t][0] = (yv[t][0]-mu0)*iv0*w0 + b0v;
            yv[t][1] = (yv[t][1]-mu0)*iv0*w1 + b1v;
            yv[t][2] = (yv[t][2]-mu1)*iv1*w0 + b0v;
            yv[t][3] = (yv[t][3]-mu1)*iv1*w1 + b1v;
        }
    }

    float* ynp = outyn + base_row*64;
    #pragma unroll
    for (int t = 0; t < 8; t++) {
        int c = t*8 + 2*tg;
        *(float2*)&ynp[(long)r0g*64 + c] = make_float2(yv[t][0], yv[t][1]);
        *(float2*)&ynp[(long)r1g*64 + c] = make_float2(yv[t][2], yv[t][3]);
    }

    uint32_t ya[4][4];
    #pragma unroll
    for (int kk = 0; kk < 4; kk++) {
        ya[kk][0] = packh2(yv[2*kk][0],   yv[2*kk][1]);
        ya[kk][1] = packh2(yv[2*kk][2],   yv[2*kk][3]);
        ya[kk][2] = packh2(yv[2*kk+1][0], yv[2*kk+1][1]);
        ya[kk][3] = packh2(yv[2*kk+1][2], yv[2*kk+1][3]);
    }

    uint32_t adKW = smem_u32(kwh) + ((lj>>1)*8 + lr)*(WST*2) + (lj&1)*16;
    uint32_t adVW = smem_u32(vwh) + ((lj>>1)*8 + lr)*(WST*2) + (lj&1)*16;

    float ck[4][4];
    #pragma unroll
    for (int tn = 0; tn < 4; tn++) { ck[tn][0]=ck[tn][1]=ck[tn][2]=ck[tn][3]=0.0f; }
    #pragma unroll
    for (int kk = 0; kk < 4; kk++) {
        #pragma unroll
        for (int tp = 0; tp < 2; tp++) {
            uint32_t b0, b1, b2, b3;
            ldsm_x4(b0, b1, b2, b3, adKW + tp*(16*WST*2) + kk*32);
            mma_f16(ck[2*tp  ], ya[kk], b0, b1);
            mma_f16(ck[2*tp+1], ya[kk], b2, b3);
        }
    }
    {
        __half* kp = out_k + base_row*32;
        #pragma unroll
        for (int tn = 0; tn < 4; tn++) {
            int c0 = tn*8 + 2*tg;
            float b0v = kb_s[c0], b1v = kb_s[c0+1];
            *(__half2*)&kp[(long)r0g*32 + c0] =
                __floats2half2_rn(ck[tn][0]+b0v, ck[tn][1]+b1v);
            *(__half2*)&kp[(long)r1g*32 + c0] =
                __floats2half2_rn(ck[tn][2]+b0v, ck[tn][3]+b1v);
        }
    }

    float co[8][4];
    #pragma unroll
    for (int t = 0; t < 8; t++) { co[t][0]=co[t][1]=co[t][2]=co[t][3]=0.0f; }
    #pragma unroll
    for (int kk = 0; kk < 4; kk++) {
        #pragma unroll
        for (int tp = 0; tp < 4; tp++) {
            uint32_t b0, b1, b2, b3;
            ldsm_x4(b0, b1, b2, b3, adVW + tp*(16*WST*2) + kk*32);
            mma_f16(co[2*tp  ], ya[kk], b0, b1);
            mma_f16(co[2*tp+1], ya[kk], b2, b3);
        }
    }
    #pragma unroll
    for (int t = 0; t < 8; t++) {
        int c0 = t*8 + 2*tg;
        float b0v = vb_s[c0], b1v = vb_s[c0+1];
        *(__half2*)&v_s[r0g*VS_ST + c0] =
            __floats2half2_rn(co[t][0]+b0v, co[t][1]+b1v);
        *(__half2*)&v_s[r1g*VS_ST + c0] =
            __floats2half2_rn(co[t][2]+b0v, co[t][3]+b1v);
    }
    __syncthreads();

    long bb  = base_row >> 10;
    int  rin = (int)(base_row & 1023);
    #pragma unroll
    for (int it = 0; it < 16; it++) {
        int idx = tid + it*256;
        int d  = idx >> 6;
        int s2 = (idx & 63) * 2;
        __half2 hv = __halves2half2(v_s[s2*VS_ST + d], v_s[(s2+1)*VS_ST + d]);
        *(__half2*)&out_vT[(bb*64 + d)*1024 + rin + s2] = hv;
    }
}

// ---------------------------------------------------------------------------
// Fused kernel: LN1(regs) -> q-proj(mma) -> flash attn (f16-accum S mma,
// triple-buffered cp.async w/ 1 sync per tile, deg-2 half2 exp) ->
// LN3(regs) -> MLP(mma) + residual -> out.
// ---------------------------------------------------------------------------
#define KST 40   // K smem stride (halfs)
#define VST 72   // VT smem stride (halfs)

#define KSZ (64*KST*2)                      // 5120
#define VSZ (64*VST*2)                      // 9216
#define OFF_K0   0
#define OFF_K1   (OFF_K0 + KSZ)
#define OFF_K2   (OFF_K1 + KSZ)
#define OFF_V0   (OFF_K2 + KSZ)             // 15360
#define OFF_V1   (OFF_V0 + VSZ)
#define OFF_V2   (OFF_V1 + VSZ)
#define OFF_QWH  (OFF_V2 + VSZ)             // 43008  [32][72] halfs
#define OFF_IWH  (OFF_QWH + 32*WST*2)       // 47616
#define OFF_OWH  (OFF_IWH + 32*WST*2)       // 52224  [64][40]
#define OFF_PAR  (OFF_OWH + 64*OST*2)       // 57344
#define SMEM_BYTES (OFF_PAR + 384*4)        // 58880

__global__ void __launch_bounds__(256, 2) attn_kernel(
    const float* __restrict__ x,
    const float* __restrict__ ln1w, const float* __restrict__ ln1b,
    const float* __restrict__ qw,   const float* __restrict__ qb,
    const float* __restrict__ ln3w, const float* __restrict__ ln3b,
    const float* __restrict__ inw,  const float* __restrict__ inb,
    const float* __restrict__ outw, const float* __restrict__ outb,
    float* __restrict__ out1)
{
    extern __shared__ char smraw[];
    __half* qwh = (__half*)(smraw + OFF_QWH);
    __half* iwh = (__half*)(smraw + OFF_IWH);
    __half* owh = (__half*)(smraw + OFF_OWH);
    float*  par = (float*)(smraw + OFF_PAR);
    float*  ln1w_s = par;        float* ln1b_s = par + 64;
    float*  ln3w_s = par + 128;  float* ln3b_s = par + 192;
    float*  qb_s   = par + 256;  float* inb_s  = par + 288;
    float*  outb_s = par + 320;

    int b   = blockIdx.y;
    int q0  = blockIdx.x * BQ;
    int tid = threadIdx.x;
    int warp = tid >> 5, lane = tid & 31;
    int g = lane >> 2, tg = lane & 3;
    int R0 = warp * 16;
    int r0g = R0 + g, r1g = R0 + 8 + g;
    const float CSCALE = 0.2550352733f;   // log2(e)/sqrt(32)

    // ---- pipeline setup + start tiles 0,1 immediately ----
    int lj = lane >> 3, lr = lane & 7;
    uint32_t koff = (((lj>>1)*8 + lr)*KST + (lj&1)*8)*2;
    uint32_t voff = (((lj>>1)*8 + lr)*VST + (lj&1)*8)*2;
    uint32_t kb3[3] = { smem_u32(smraw + OFF_K0), smem_u32(smraw + OFF_K1),
                        smem_u32(smraw + OFF_K2) };
    uint32_t vb3[3] = { smem_u32(smraw + OFF_V0), smem_u32(smraw + OFF_V1),
                        smem_u32(smraw + OFF_V2) };
    const __half* kgp = g_k  + (long)b*LSEQ*DQK;
    const __half* vgp = g_vT + (long)b*DIM*LSEQ;

    auto issue_tile = [&](int kt, int s) {
        {   // K tile: 64 rows x 64 B
            int row = tid >> 2, c16 = tid & 3;
            cp_async16(kb3[s] + row*(KST*2) + c16*16,
                       (const char*)(kgp + (long)(kt)*DQK) + row*64 + c16*16);
        }
        #pragma unroll
        for (int it = 0; it < 2; it++) {   // V tile: 64 d-rows x 128 B
            int idx = tid + it*256;
            int d = idx >> 3, c16 = idx & 7;
            cp_async16(vb3[s] + d*(VST*2) + c16*16,
                       (const char*)(vgp + (long)d*LSEQ + kt) + c16*16);
        }
        CP_COMMIT();
    };
    issue_tile(0, 0);
    issue_tile(BK, 1);

    // ---- weights (fp16) + params to smem ----
    for (int i = tid; i < 32*64; i += 256) {
        int r = i >> 6, c = i & 63;
        qwh[r*WST + c] = __float2half_rn(qw[i]);
        iwh[r*WST + c] = __float2half_rn(inw[i]);
    }
    for (int i = tid; i < 64*32; i += 256)
        owh[(i>>5)*OST + (i&31)] = __float2half_rn(outw[i]);
    if (tid < 64) {
        ln1w_s[tid]=ln1w[tid]; ln1b_s[tid]=ln1b[tid];
        ln3w_s[tid]=ln3w[tid]; ln3b_s[tid]=ln3b[tid];
        outb_s[tid]=outb[tid];
    } else if (tid < 96) { qb_s[tid-64]=qb[tid-64]; inb_s[tid-64]=inb[tid-64]; }

    // ---- x -> fragment-layout registers ----
    float xv[8][4];
    const float* xpb = x + ((long)b*LSEQ + q0)*DIM;
    #pragma unroll
    for (int t = 0; t < 8; t++) {
        int c = t*8 + 2*tg;
        float2 v0 = *(const float2*)&xpb[(long)r0g*64 + c];
        float2 v1 = *(const float2*)&xpb[(long)r1g*64 + c];
        xv[t][0]=v0.x; xv[t][1]=v0.y; xv[t][2]=v1.x; xv[t][3]=v1.y;
    }
    __syncthreads();   // weights/params visible

    // ---- LN1 in registers ----
    {
        float s0=0, ss0=0, s1=0, ss1=0;
        #pragma unroll
        for (int t = 0; t < 8; t++) {
            s0 += xv[t][0]+xv[t][1]; ss0 += xv[t][0]*xv[t][0]+xv[t][1]*xv[t][1];
            s1 += xv[t][2]+xv[t][3]; ss1 += xv[t][2]*xv[t][2]+xv[t][3]*xv[t][3];
        }
        s0 = quad_sum(s0); ss0 = quad_sum(ss0);
        s1 = quad_sum(s1); ss1 = quad_sum(ss1);
        float mu0 = s0*(1.0f/64.0f), mu1 = s1*(1.0f/64.0f);
        float iv0 = rsqrtf(ss0*(1.0f/64.0f) - mu0*mu0 + 1e-5f);
        float iv1 = rsqrtf(ss1*(1.0f/64.0f) - mu1*mu1 + 1e-5f);
        #pragma unroll
        for (int t = 0; t < 8; t++) {
            int c = t*8 + 2*tg;
            float w0 = ln1w_s[c], w1 = ln1w_s[c+1];
            float b0v= ln1b_s[c], b1v= ln1b_s[c+1];
            xv[t][0] = (xv[t][0]-mu0)*iv0*w0 + b0v;
            xv[t][1] = (xv[t][1]-mu0)*iv0*w1 + b1v;
            xv[t][2] = (xv[t][2]-mu1)*iv1*w0 + b0v;
            xv[t][3] = (xv[t][3]-mu1)*iv1*w1 + b1v;
        }
    }

    // ---- q-proj via mma ----
    uint32_t adQW = smem_u32(qwh) + ((lj>>1)*8 + lr)*(WST*2) + (lj&1)*16;
    uint32_t adIW = smem_u32(iwh) + ((lj>>1)*8 + lr)*(WST*2) + (lj&1)*16;
    uint32_t adOW = smem_u32(owh) + ((lj>>1)*8 + lr)*(OST*2) + (lj&1)*16;

    float cq[4][4];
    #pragma unroll
    for (int tn = 0; tn < 4; tn++) { cq[tn][0]=cq[tn][1]=cq[tn][2]=cq[tn][3]=0.0f; }
    #pragma unroll
    for (int kk = 0; kk < 4; kk++) {
        uint32_t xa[4] = { packh2(xv[2*kk][0],   xv[2*kk][1]),
                           packh2(xv[2*kk][2],   xv[2*kk][3]),
                           packh2(xv[2*kk+1][0], xv[2*kk+1][1]),
                           packh2(xv[2*kk+1][2], xv[2*kk+1][3]) };
        #pragma unroll
        for (int tp = 0; tp < 2; tp++) {
            uint32_t b0, b1, b2, b3;
            ldsm_x4(b0, b1, b2, b3, adQW + tp*(16*WST*2) + kk*32);
            mma_f16(cq[2*tp  ], xa, b0, b1);
            mma_f16(cq[2*tp+1], xa, b2, b3);
        }
    }
    uint32_t qa[2][4];
    #pragma unroll
    for (int kk = 0; kk < 2; kk++) {
        float bA0 = qb_s[8*(2*kk)+2*tg],   bA1 = qb_s[8*(2*kk)+2*tg+1];
        float bB0 = qb_s[8*(2*kk+1)+2*tg], bB1 = qb_s[8*(2*kk+1)+2*tg+1];
        qa[kk][0] = packh2((cq[2*kk][0]+bA0)*CSCALE,   (cq[2*kk][1]+bA1)*CSCALE);
        qa[kk][1] = packh2((cq[2*kk][2]+bA0)*CSCALE,   (cq[2*kk][3]+bA1)*CSCALE);
        qa[kk][2] = packh2((cq[2*kk+1][0]+bB0)*CSCALE, (cq[2*kk+1][1]+bB1)*CSCALE);
        qa[kk][3] = packh2((cq[2*kk+1][2]+bB0)*CSCALE, (cq[2*kk+1][3]+bB1)*CSCALE);
    }

    // ---- flash attention main loop: 1 sync/tile, f16-accum S ----
    float o[8][4];
    #pragma unroll
    for (int t = 0; t < 8; t++) { o[t][0]=o[t][1]=o[t][2]=o[t][3]=0.0f; }
    float sum0 = 0.0f, sum1 = 0.0f;

    for (int i = 0; i < 16; i++) {
        if (i < 15) { CP_WAIT(1); } else { CP_WAIT(0); }
        __syncthreads();   // tile i visible to all; all reads of buf (i+2)%3 done
        if (i < 14) issue_tile((i+2)*BK, (i+2)%3);

        int bi = i % 3;
        uint32_t adK = kb3[bi] + koff;
        uint32_t adV = vb3[bi] + voff;

        // ---- S = Qs @ K^T, fp16 accumulators (packed half2 out) ----
        uint32_t e01[8], e23[8];   // reused: first S, then P=exp(S)
        #pragma unroll
        for (int t = 0; t < 8; t++) { e01[t] = 0u; e23[t] = 0u; }
        #pragma unroll
        for (int kk = 0; kk < 2; kk++) {
            #pragma unroll
            for (int tp = 0; tp < 4; tp++) {
                uint32_t b0, b1, b2, b3;
                ldsm_x4(b0, b1, b2, b3, adK + tp*(16*KST*2) + kk*32);
                uint32_t cA[2] = { e01[2*tp],   e23[2*tp]   };
                uint32_t cB[2] = { e01[2*tp+1], e23[2*tp+1] };
                mma_f16h(cA, qa[kk], b0, b1);
                mma_f16h(cB, qa[kk], b2, b3);
                e01[2*tp]=cA[0];   e23[2*tp]=cA[1];
                e01[2*tp+1]=cB[0]; e23[2*tp+1]=cB[1];
            }
        }

        // ---- P = 2^S (deg-2 half2 poly), in place ----
        #pragma unroll
        for (int t = 0; t < 8; t++) {
            e01[t] = h2_exp2_pk(*(__half2*)&e01[t]);
            e23[t] = h2_exp2_pk(*(__half2*)&e23[t]);
        }
        {
            __half2* h01 = (__half2*)e01;
            __half2* h23 = (__half2*)e23;
            __half2 a = __hadd2(__hadd2(__hadd2(h01[0],h01[1]), __hadd2(h01[2],h01[3])),
                                __hadd2(__hadd2(h01[4],h01[5]), __hadd2(h01[6],h01[7])));
            __half2 c = __hadd2(__hadd2(__hadd2(h23[0],h23[1]), __hadd2(h23[2],h23[3])),
                                __hadd2(__hadd2(h23[4],h23[5]), __hadd2(h23[6],h23[7])));
            float2 fa = __half22float2(a);
            float2 fc = __half22float2(c);
            sum0 += fa.x + fa.y;
            sum1 += fc.x + fc.y;
        }

        // ---- O += P @ V ----
        #pragma unroll
        for (int kk = 0; kk < 4; kk++) {
            uint32_t pa[4] = { e01[2*kk], e23[2*kk], e01[2*kk+1], e23[2*kk+1] };
            #pragma unroll
            for (int tp = 0; tp < 4; tp++) {
                uint32_t b0, b1, b2, b3;
                ldsm_x4(b0, b1, b2, b3, adV + tp*(16*VST*2) + kk*32);
                mma_f16(o[2*tp  ], pa, b0, b1);
                mma_f16(o[2*tp+1], pa, b2, b3);
            }
        }
    }

    // ---- normalize + residual (regs): h = xn + O/l ----
    sum0 = quad_sum(sum0);
    sum1 = quad_sum(sum1);
    float inv0 = 1.0f / sum0, inv1 = 1.0f / sum1;
    #pragma unroll
    for (int t = 0; t < 8; t++) {
        o[t][0] = xv[t][0] + o[t][0]*inv0;
        o[t][1] = xv[t][1] + o[t][1]*inv0;
        o[t][2] = xv[t][2] + o[t][2]*inv1;
        o[t][3] = xv[t][3] + o[t][3]*inv1;
    }

    // ---- LN3 in registers ----
    {
        float s0=0, ss0=0, s1=0, ss1=0;
        #pragma unroll
        for (int t = 0; t < 8; t++) {
            s0 += o[t][0]+o[t][1]; ss0 += o[t][0]*o[t][0]+o[t][1]*o[t][1];
            s1 += o[t][2]+o[t][3]; ss1 += o[t][2]*o[t][2]+o[t][3]*o[t][3];
        }
        s0 = quad_sum(s0); ss0 = quad_sum(ss0);
        s1 = quad_sum(s1); ss1 = quad_sum(ss1);
        float mu0 = s0*(1.0f/64.0f), mu1 = s1*(1.0f/64.0f);
        float iv0 = rsqrtf(ss0*(1.0f/64.0f) - mu0*mu0 + 1e-5f);
        float iv1 = rsqrtf(ss1*(1.0f/64.0f) - mu1*mu1 + 1e-5f);
        #pragma unroll
        for (int t = 0; t < 8; t++) {
            int c = t*8 + 2*tg;
            float w0 = ln3w_s[c], w1 = ln3w_s[c+1];
            float b0v= ln3b_s[c], b1v= ln3b_s[c+1];
            o[t][0] = (o[t][0]-mu0)*iv0*w0 + b0v;
            o[t][1] = (o[t][1]-mu0)*iv0*w1 + b1v;
            o[t][2] = (o[t][2]-mu1)*iv1*w0 + b0v;
            o[t][3] = (o[t][3]-mu1)*iv1*w1 + b1v;
        }
    }

    // ---- MLP hidden via mma ----
    float ch[4][4];
    #pragma unroll
    for (int tn = 0; tn < 4; tn++) { ch[tn][0]=ch[tn][1]=ch[tn][2]=ch[tn][3]=0.0f; }
    #pragma unroll
    for (int kk = 0; kk < 4; kk++) {
        uint32_t ha[4] = { packh2(o[2*kk][0],   o[2*kk][1]),
                           packh2(o[2*kk][2],   o[2*kk][3]),
                           packh2(o[2*kk+1][0], o[2*kk+1][1]),
                           packh2(o[2*kk+1][2], o[2*kk+1][3]) };
        #pragma unroll
        for (int tp = 0; tp < 2; tp++) {
            uint32_t b0, b1, b2, b3;
            ldsm_x4(b0, b1, b2, b3, adIW + tp*(16*WST*2) + kk*32);
            mma_f16(ch[2*tp  ], ha, b0, b1);
            mma_f16(ch[2*tp+1], ha, b2, b3);
        }
    }
    uint32_t pa2[2][4];
    #pragma unroll
    for (int kk = 0; kk < 2; kk++) {
        float bA0 = inb_s[8*(2*kk)+2*tg],   bA1 = inb_s[8*(2*kk)+2*tg+1];
        float bB0 = inb_s[8*(2*kk+1)+2*tg], bB1 = inb_s[8*(2*kk+1)+2*tg+1];
        pa2[kk][0] = packh2(fmaxf(ch[2*kk][0]+bA0, 0.0f),   fmaxf(ch[2*kk][1]+bA1, 0.0f));
        pa2[kk][1] = packh2(fmaxf(ch[2*kk][2]+bA0, 0.0f),   fmaxf(ch[2*kk][3]+bA1, 0.0f));
        pa2[kk][2] = packh2(fmaxf(ch[2*kk+1][0]+bB0, 0.0f), fmaxf(ch[2*kk+1][1]+bB1, 0.0f));
        pa2[kk][3] = packh2(fmaxf(ch[2*kk+1][2]+bB0, 0.0f), fmaxf(ch[2*kk+1][3]+bB1, 0.0f));
    }

    // ---- MLP out via mma ----
    float co[8][4];
    #pragma unroll
    for (int t = 0; t < 8; t++) { co[t][0]=co[t][1]=co[t][2]=co[t][3]=0.0f; }
    #pragma unroll
    for (int kk = 0; kk < 2; kk++) {
        #pragma unroll
        for (int tp = 0; tp < 4; tp++) {
            uint32_t b0, b1, b2, b3;
            ldsm_x4(b0, b1, b2, b3, adOW + tp*(16*OST*2) + kk*32);
            mma_f16(co[2*tp  ], pa2[kk], b0, b1);
            mma_f16(co[2*tp+1], pa2[kk], b2, b3);
        }
    }

    // ---- out1 = hn + mlp + outb ----
    float* op = out1 + ((long)b*LSEQ + q0)*DIM;
    #pragma unroll
    for (int t = 0; t < 8; t++) {
        int c = t*8 + 2*tg;
        float ob0 = outb_s[c], ob1 = outb_s[c+1];
        *(float2*)&op[(long)r0g*64 + c] =
            make_float2(o[t][0] + co[t][0] + ob0, o[t][1] + co[t][1] + ob1);
        *(float2*)&op[(long)r1g*64 + c] =
            make_float2(o[t][2] + co[t][2] + ob0, o[t][3] + co[t][3] + ob1);
    }
}

// ---------------------------------------------------------------------------
extern "C" void kernel_launch(void* const* d_in, const int* in_sizes, int n_in,
                              void* d_out, int out_size)
{
    const float* x    = (const float*)d_in[0];
    const float* y    = (const float*)d_in[1];
    const float* ln1w = (const float*)d_in[2];
    const float* ln1b = (const float*)d_in[3];
    const float* ln2w = (const float*)d_in[4];
    const float* ln2b = (const float*)d_in[5];
    const float* ln3w = (const float*)d_in[6];
    const float* ln3b = (const float*)d_in[7];
    const float* qw   = (const float*)d_in[8];
    const float* qb   = (const float*)d_in[9];
    const float* kw   = (const float*)d_in[10];
    const float* kb   = (const float*)d_in[11];
    const float* vw   = (const float*)d_in[12];
    const float* vb   = (const float*)d_in[13];
    const float* inw  = (const float*)d_in[14];
    const float* inb  = (const float*)d_in[15];
    const float* outw = (const float*)d_in[16];
    const float* outb = (const float*)d_in[17];

    float* out1  = (float*)d_out;                    // hn + mlp
    float* outyn = out1 + (size_t)NB*LSEQ*DIM;       // yn

    __half *p_k, *p_vT;
    cudaGetSymbolAddress((void**)&p_k,  g_k);
    cudaGetSymbolAddress((void**)&p_vT, g_vT);

    ln_proj_y_tc<<<NB*LSEQ/128, 256>>>(y, ln2w, ln2b, kw, kb, vw, vb,
                                       outyn, p_k, p_vT);

    cudaFuncSetAttribute(attn_kernel, cudaFuncAttributeMaxDynamicSharedMemorySize,
                         SMEM_BYTES);
    attn_kernel<<<dim3(LSEQ/BQ, NB), 256, SMEM_BYTES>>>(
        x, ln1w, ln1b, qw, qb, ln3w, ln3b, inw, inb, outw, outb, out1);
}